// round 6
// baseline (speedup 1.0000x reference)
#include <cuda_runtime.h>
#include <cuda_fp16.h>
#include <math.h>

#define Bc   4
#define C    48
#define C3   144
#define HH   256
#define WW   256
#define NPIX 65536   // HH*WW

typedef unsigned long long u64;

// packed f32x2 helpers (sm_100+: fma.rn.f32x2 = 2 fp32 FMAs / instruction)
__device__ __forceinline__ void ffma2(u64& d, u64 a, u64 b, u64 c) {
    asm("fma.rn.f32x2 %0, %1, %2, %3;" : "=l"(d) : "l"(a), "l"(b), "l"(c));
}
__device__ __forceinline__ u64 pack2(float x, float y) {
    u64 r; asm("mov.b64 %0, {%1, %2};" : "=l"(r) : "f"(x), "f"(y)); return r;
}
__device__ __forceinline__ void unpack2(float& x, float& y, u64 v) {
    asm("mov.b64 {%0, %1}, %2;" : "=f"(x), "=f"(y) : "l"(v));
}

// ---- scratch (device globals: no allocation allowed) ----
__device__ __half g_qkv[(size_t)Bc * C3 * NPIX];   // after 1x1 conv (75 MB)
__device__ __half g_dw [(size_t)Bc * C3 * NPIX];   // after depthwise (75 MB)
__device__ float  g_small[Bc * (C * C + 2 * C)];   // gram | qss | kss

// ============================================================
// K1: qkv 1x1 conv as GEMM W[144,48] x X[48, 64px-tile].
// 288 thr = 18 ocg(8 oc) x 16 pxg(4 px). Accumulators packed over
// (oc,oc+1); w-pairs native u64 from k-major smem; x pre-duplicated
// (x,x) in smem. Per k: 4 LDS.128 vs 16 FFMA2 -> FMA-bound.
// k chunked by 24 (smem 26 KB).
// ============================================================
__global__ void __launch_bounds__(288) k_qkv(const float* __restrict__ x,
                                             const float* __restrict__ w) {
    __shared__ float Ws[24][C3];                 // Ws[k][oc], 13.8 KB
    __shared__ __align__(16) u64 Xs[24][64];     // dup px, 12.3 KB
    const int tid = threadIdx.x;
    const int b   = blockIdx.x >> 10;            // 1024 tiles / batch
    const int px0 = (blockIdx.x & 1023) << 6;    // 64 px / block
    const int pxg = tid & 15;                    // 0..15
    const int ocg = tid >> 4;                    // 0..17
    const int oc0 = ocg * 8;
    const int xb  = pxg * 4;                     // u64 index into Xs row

    const float* xb_p = x + (size_t)b * C * NPIX + px0;

    u64 acc[4][4];
#pragma unroll
    for (int i = 0; i < 4; i++)
#pragma unroll
        for (int j = 0; j < 4; j++) acc[i][j] = 0ull;

#pragma unroll 1
    for (int kc = 0; kc < C; kc += 24) {
        __syncthreads();
        // stage weights k-major
        for (int i = tid; i < 24 * C3; i += 288) {
            int kk = i / C3, oc = i % C3;
            Ws[kk][oc] = w[oc * C + kc + kk];
        }
        // stage x, duplicated (x,x)
        for (int i = tid; i < 24 * 16; i += 288) {
            int kk = i >> 4, q = i & 15;
            float4 v = *(const float4*)(xb_p + (size_t)(kc + kk) * NPIX + (q << 2));
            u64* dst = &Xs[kk][q * 4];
            uint4 d0, d1;
            *(u64*)&d0.x = pack2(v.x, v.x); *(u64*)&d0.z = pack2(v.y, v.y);
            *(u64*)&d1.x = pack2(v.z, v.z); *(u64*)&d1.z = pack2(v.w, v.w);
            *(uint4*)&dst[0] = d0; *(uint4*)&dst[2] = d1;
        }
        __syncthreads();
#pragma unroll 8
        for (int kk = 0; kk < 24; kk++) {
            ulonglong2 wa = *(const ulonglong2*)&Ws[kk][oc0];
            ulonglong2 wb = *(const ulonglong2*)&Ws[kk][oc0 + 4];
            u64 xv[4];
            *(uint4*)&xv[0] = *(const uint4*)&Xs[kk][xb];
            *(uint4*)&xv[2] = *(const uint4*)&Xs[kk][xb + 2];
            u64 wp[4] = {wa.x, wa.y, wb.x, wb.y};
#pragma unroll
            for (int i = 0; i < 4; i++)
#pragma unroll
                for (int j = 0; j < 4; j++) ffma2(acc[i][j], wp[i], xv[j], acc[i][j]);
        }
    }

    __half* ob = g_qkv + (size_t)b * C3 * NPIX + px0 + pxg * 4;
#pragma unroll
    for (int o = 0; o < 8; o++) {
        const int ocp = o >> 1, hi = o & 1;
        float f[4];
#pragma unroll
        for (int j = 0; j < 4; j++) {
            float lo, h; unpack2(lo, h, acc[ocp][j]);
            f[j] = hi ? h : lo;
        }
        uint2 st;
        *(__half2*)&st.x = __floats2half2_rn(f[0], f[1]);
        *(__half2*)&st.y = __floats2half2_rn(f[2], f[3]);
        *(uint2*)(ob + (size_t)(oc0 + o) * NPIX) = st;
    }
}

// ============================================================
// K2: depthwise 3x3, pad 1. Block = (b,ch,8-row tile), 256 threads.
// ============================================================
#define DWROWS 8
__global__ __launch_bounds__(256) void k_dw(const float* __restrict__ w) {
    const int tilesY = HH / DWROWS;
    const int ytile = blockIdx.x & (tilesY - 1);
    const int ch    = (blockIdx.x / tilesY) % C3;
    const int b     = blockIdx.x / (tilesY * C3);
    const int tid   = threadIdx.x;

    const __half* in  = g_qkv + ((size_t)b * C3 + ch) * NPIX;
    __half*       out = g_dw  + ((size_t)b * C3 + ch) * NPIX;

    __shared__ float rows[DWROWS + 2][WW];
    const int y0 = ytile * DWROWS;
    for (int i = tid; i < (DWROWS + 2) * (WW / 2); i += 256) {
        int r = i / (WW / 2), c2 = i % (WW / 2);
        int y = y0 - 1 + r;
        float2 v = make_float2(0.f, 0.f);
        if (y >= 0 && y < HH)
            v = __half22float2(*(const __half2*)(in + y * WW + 2 * c2));
        rows[r][2 * c2] = v.x; rows[r][2 * c2 + 1] = v.y;
    }
    __syncthreads();

    const float w00 = w[ch*9+0], w01 = w[ch*9+1], w02 = w[ch*9+2];
    const float w10 = w[ch*9+3], w11 = w[ch*9+4], w12 = w[ch*9+5];
    const float w20 = w[ch*9+6], w21 = w[ch*9+7], w22 = w[ch*9+8];

    const int half = tid >> 7;
    const int c2   = tid & 127;
    const int col0 = 2 * c2, col1 = col0 + 1;
    const float lm = (c2 > 0) ? 1.f : 0.f;
    const float rm = (c2 < 127) ? 1.f : 0.f;
    const int xl = max(col0 - 1, 0), xr = min(col1 + 1, WW - 1);

#pragma unroll
    for (int rr = 0; rr < DWROWS / 2; rr++) {
        const int r = 2 * rr + half;
        const float* r0 = rows[r], *r1 = rows[r + 1], *r2 = rows[r + 2];
        float a0 = r0[xl] * lm, b0 = r0[col0], c0v = r0[col1], d0 = r0[xr] * rm;
        float a1 = r1[xl] * lm, b1 = r1[col0], c1v = r1[col1], d1 = r1[xr] * rm;
        float a2 = r2[xl] * lm, b2 = r2[col0], c2v = r2[col1], d2 = r2[xr] * rm;
        float acc0 = w00*a0 + w01*b0 + w02*c0v + w10*a1 + w11*b1 + w12*c1v + w20*a2 + w21*b2 + w22*c2v;
        float acc1 = w00*b0 + w01*c0v + w02*d0 + w10*b1 + w11*c1v + w12*d1 + w20*b2 + w21*c2v + w22*d2;
        *(__half2*)(out + (y0 + r) * WW + col0) = __floats2half2_rn(acc0, acc1);
    }
}

// ============================================================
// K3: Gram G = Q K^T (48x48) + squared norms; FFMA2 over px pairs.
// ============================================================
#define TS2   32
#define CHUNK 1024
__global__ __launch_bounds__(256) void k_gram() {
    const int chunks = NPIX / CHUNK;
    const int b     = blockIdx.x / chunks;
    const int cbase = (blockIdx.x % chunks) * CHUNK;

    __shared__ float2 Qs[C][TS2 + 1], Ks[C][TS2 + 1];
    const int tid = threadIdx.x;
    const int c0 = (tid >> 4) * 3;
    const int d0 = (tid & 15) * 3;

    const __half* Q = g_dw + (size_t)b * C3 * NPIX;
    const __half* K = g_dw + (size_t)b * C3 * NPIX + (size_t)C * NPIX;

    u64 acc[3][3];
#pragma unroll
    for (int i = 0; i < 3; i++)
#pragma unroll
        for (int j = 0; j < 3; j++) acc[i][j] = 0ull;
    u64 sqa = 0ull;

    for (int sub = 0; sub < CHUNK / (2 * TS2); sub++) {
        const int tb = cbase + sub * (2 * TS2);
        for (int i = tid; i < C * TS2; i += 256) {
            int cc = i / TS2, t = i % TS2;
            Qs[cc][t] = __half22float2(*(const __half2*)(Q + (size_t)cc * NPIX + tb + 2 * t));
            Ks[cc][t] = __half22float2(*(const __half2*)(K + (size_t)cc * NPIX + tb + 2 * t));
        }
        __syncthreads();
#pragma unroll 4
        for (int t = 0; t < TS2; t++) {
            u64 q0 = *(const u64*)&Qs[c0][t];
            u64 q1 = *(const u64*)&Qs[c0 + 1][t];
            u64 q2 = *(const u64*)&Qs[c0 + 2][t];
            u64 k0 = *(const u64*)&Ks[d0][t];
            u64 k1 = *(const u64*)&Ks[d0 + 1][t];
            u64 k2 = *(const u64*)&Ks[d0 + 2][t];
            ffma2(acc[0][0], q0, k0, acc[0][0]); ffma2(acc[0][1], q0, k1, acc[0][1]); ffma2(acc[0][2], q0, k2, acc[0][2]);
            ffma2(acc[1][0], q1, k0, acc[1][0]); ffma2(acc[1][1], q1, k1, acc[1][1]); ffma2(acc[1][2], q1, k2, acc[1][2]);
            ffma2(acc[2][0], q2, k0, acc[2][0]); ffma2(acc[2][1], q2, k1, acc[2][1]); ffma2(acc[2][2], q2, k2, acc[2][2]);
            if (tid < C)          { u64 v = *(const u64*)&Qs[tid][t];     ffma2(sqa, v, v, sqa); }
            else if (tid < 2 * C) { u64 v = *(const u64*)&Ks[tid - C][t]; ffma2(sqa, v, v, sqa); }
        }
        __syncthreads();
    }

    float* gbase = g_small + b * (C * C + 2 * C);
#pragma unroll
    for (int i = 0; i < 3; i++)
#pragma unroll
        for (int j = 0; j < 3; j++) {
            float lo, hi; unpack2(lo, hi, acc[i][j]);
            atomicAdd(&gbase[(c0 + i) * C + (d0 + j)], lo + hi);
        }
    if (tid < 2 * C) { float lo, hi; unpack2(lo, hi, sqa); atomicAdd(&gbase[C * C + tid], lo + hi); }
}

// ============================================================
// K4 (fused attn + out): prologue recomputes softmax + Ms[d][oc]
// from g_small (cheap, fully parallel across blocks), then
// out = M @ V as GEMM over a 64-px tile, same packing as k_qkv.
// 192 thr = 12 ocg(4 oc) x 16 pxg(4 px). Smem: Ms + union(head|Xs).
// ============================================================
#define OUT_HEAD_BYTES (C*(C+1)*4 + C*C*4 + 2*C*4)   // A + P + qn + kn = 19008
#define OUT_XS_BYTES   (C*64*8)                      // 24576
__global__ void __launch_bounds__(192) k_out(const float* __restrict__ proj,
                                             const float* __restrict__ temp,
                                             float* __restrict__ out) {
    __shared__ float Ms[C][C];                       // Ms[d][oc] = M[oc][d]
    __shared__ __align__(16) char shbuf[OUT_XS_BYTES];  // union: head | Xs
    float (*A)[C + 1] = (float(*)[C + 1])shbuf;
    float* P  = (float*)(shbuf + C * (C + 1) * 4);
    float* qn = (float*)(shbuf + C * (C + 1) * 4 + C * C * 4);
    float* kn = qn + C;
    u64 (*Xs)[64] = (u64(*)[64])shbuf;

    const int tid = threadIdx.x, warp = tid >> 5, lane = tid & 31;
    const int b   = blockIdx.x >> 10;
    const int px0 = (blockIdx.x & 1023) << 6;
    const int pxg = tid & 15;
    const int ocg = tid >> 4;                        // 0..11
    const int oc0 = ocg * 4;
    const int xbq = pxg * 4;

    const float* gbase = g_small + b * (C * C + 2 * C);
    const float T = temp[0];

    // ---- head: softmax + M = proj @ attn ----
    for (int i = tid; i < C * C; i += 192) P[i] = proj[i];
    if (tid < C)          qn[tid]     = fmaxf(sqrtf(gbase[C * C + tid]), 1e-12f);
    else if (tid < 2 * C) kn[tid - C] = fmaxf(sqrtf(gbase[C * C + tid]), 1e-12f);
    __syncthreads();

    for (int i = tid; i < C * C; i += 192) {
        int r = i / C, d = i % C;
        A[r][d] = gbase[i] * T / (qn[r] * kn[d]);
    }
    __syncthreads();

    for (int r = warp; r < C; r += 6) {
        float v0 = A[r][lane];
        float v1 = (lane + 32 < C) ? A[r][lane + 32] : -1e30f;
        float mx = fmaxf(v0, v1);
#pragma unroll
        for (int o = 16; o > 0; o >>= 1) mx = fmaxf(mx, __shfl_xor_sync(~0u, mx, o));
        float e0 = expf(v0 - mx);
        float e1 = (lane + 32 < C) ? expf(v1 - mx) : 0.f;
        float s = e0 + e1;
#pragma unroll
        for (int o = 16; o > 0; o >>= 1) s += __shfl_xor_sync(~0u, s, o);
        float inv = 1.f / s;
        A[r][lane] = e0 * inv;
        if (lane + 32 < C) A[r][lane + 32] = e1 * inv;
    }
    __syncthreads();

    for (int i = tid; i < C * C; i += 192) {
        const int oc = i % C, d = i / C;
        float a = 0.f;
#pragma unroll
        for (int cc = 0; cc < C; cc++) a += P[oc * C + cc] * A[cc][d];
        Ms[d][oc] = a;
    }
    __syncthreads();

    // ---- stage V tile, duplicated (v,v) (overwrites head region) ----
    const __half* vb = g_dw + (size_t)b * C3 * NPIX + (size_t)(2 * C) * NPIX + px0;
    for (int i = tid; i < C * 16; i += 192) {
        int kk = i >> 4, q = i & 15;
        uint2 raw = *(const uint2*)(vb + (size_t)kk * NPIX + (q << 2));
        float2 f01 = __half22float2(*(__half2*)&raw.x);
        float2 f23 = __half22float2(*(__half2*)&raw.y);
        u64* dst = &Xs[kk][q * 4];
        uint4 d0, d1;
        *(u64*)&d0.x = pack2(f01.x, f01.x); *(u64*)&d0.z = pack2(f01.y, f01.y);
        *(u64*)&d1.x = pack2(f23.x, f23.x); *(u64*)&d1.z = pack2(f23.y, f23.y);
        *(uint4*)&dst[0] = d0; *(uint4*)&dst[2] = d1;
    }
    __syncthreads();

    // ---- GEMM: out[oc, px] = sum_d Ms[d][oc] * V[d][px] ----
    u64 acc[2][4];
#pragma unroll
    for (int i = 0; i < 2; i++)
#pragma unroll
        for (int j = 0; j < 4; j++) acc[i][j] = 0ull;

#pragma unroll 8
    for (int kk = 0; kk < C; kk++) {
        ulonglong2 wa = *(const ulonglong2*)&Ms[kk][oc0];
        u64 xv[4];
        *(uint4*)&xv[0] = *(const uint4*)&Xs[kk][xbq];
        *(uint4*)&xv[2] = *(const uint4*)&Xs[kk][xbq + 2];
#pragma unroll
        for (int j = 0; j < 4; j++) ffma2(acc[0][j], wa.x, xv[j], acc[0][j]);
#pragma unroll
        for (int j = 0; j < 4; j++) ffma2(acc[1][j], wa.y, xv[j], acc[1][j]);
    }

    float* ob = out + (size_t)b * C * NPIX + px0 + pxg * 4;
#pragma unroll
    for (int o = 0; o < 4; o++) {
        const int ocp = o >> 1, hi = o & 1;
        float f[4];
#pragma unroll
        for (int j = 0; j < 4; j++) {
            float lo, h; unpack2(lo, h, acc[ocp][j]);
            f[j] = hi ? h : lo;
        }
        *(float4*)(ob + (size_t)(oc0 + o) * NPIX) = make_float4(f[0], f[1], f[2], f[3]);
    }
}

// ============================================================
extern "C" void kernel_launch(void* const* d_in, const int* in_sizes, int n_in,
                              void* d_out, int out_size) {
    const float* x      = (const float*)d_in[0];
    const float* qkv_w  = (const float*)d_in[1];
    const float* dw_w   = (const float*)d_in[2];
    const float* proj_w = (const float*)d_in[3];
    const float* temp   = (const float*)d_in[4];

    void* smallp = nullptr;
    cudaGetSymbolAddress(&smallp, g_small);
    cudaMemsetAsync(smallp, 0, sizeof(float) * Bc * (C * C + 2 * C));

    k_qkv <<<Bc * 1024,               288>>>(x, qkv_w);
    k_dw  <<<Bc * C3 * (HH / DWROWS), 256>>>(dw_w);
    k_gram<<<Bc * (NPIX / CHUNK),     256>>>();
    k_out <<<Bc * 1024,               192>>>(proj_w, temp, (float*)d_out);
}